// round 14
// baseline (speedup 1.0000x reference)
#include <cuda_runtime.h>
#include <cuda_fp16.h>
#include <cstdint>

#define NN     4096
#define UNITS  64
#define CC     4224              // 64 batches * 66 features, col = b*66+f
#define BNROWS 262144
#define SSCALE 1024.0f
#define KOUT_K 400               // out-GEMM K: 5 m-segments * 80 (66 valid, pad 0)
#define XSTR   ((size_t)NN*CC)

// ---------------- scratch ----------------
__device__ __align__(256) __half g_S16[(size_t)2*NN*NN];      // supports fp16, x1024 (S0|S1)
__device__ __align__(256) __half g_Xh[2][5][XSTR];            // x0..x4 fp16, double-buffered per round
__device__ __align__(256) __half g_Uh[(size_t)BNROWS*64];     // u gate (fp16, compact)
__device__ __align__(256) __half g_Rh[(size_t)BNROWS*64];     // r gate (fp16, compact)
__device__ __align__(256) __half g_W2r[KOUT_K*64];            // rearranged weights: r half of w_fn
__device__ __align__(256) __half g_W2u[KOUT_K*64];            // u half of w_fn
__device__ __align__(256) __half g_W2g[KOUT_K*64];            // w_g

// ---------------- helpers ----------------
__device__ __forceinline__ uint32_t saddr(const void* p){
  return (uint32_t)__cvta_generic_to_shared(p);
}
__device__ __forceinline__ void cpa16(uint32_t s, const void* g){
  asm volatile("cp.async.cg.shared.global [%0], [%1], 16;" :: "r"(s), "l"(g));
}
__device__ __forceinline__ void cpa4z(uint32_t s, const void* g, int srcsz){
  asm volatile("cp.async.ca.shared.global [%0], [%1], 4, %2;"
               :: "r"(s), "l"(g), "r"(srcsz));
}
__device__ __forceinline__ void cpcommit(){ asm volatile("cp.async.commit_group;"); }
template<int N_> __device__ __forceinline__ void cpwait(){
  asm volatile("cp.async.wait_group %0;" :: "n"(N_));
}
__device__ __forceinline__ void ldsm4(uint32_t* r, uint32_t a){
  asm volatile("ldmatrix.sync.aligned.m8n8.x4.shared.b16 {%0,%1,%2,%3}, [%4];"
    : "=r"(r[0]),"=r"(r[1]),"=r"(r[2]),"=r"(r[3]) : "r"(a));
}
__device__ __forceinline__ void ldsm4t(uint32_t* r, uint32_t a){
  asm volatile("ldmatrix.sync.aligned.m8n8.x4.trans.shared.b16 {%0,%1,%2,%3}, [%4];"
    : "=r"(r[0]),"=r"(r[1]),"=r"(r[2]),"=r"(r[3]) : "r"(a));
}
__device__ __forceinline__ void mma16816(float* c, const uint32_t* a, const uint32_t* b){
  asm volatile("mma.sync.aligned.m16n8k16.row.col.f32.f16.f16.f32 "
    "{%0,%1,%2,%3},{%4,%5,%6,%7},{%8,%9},{%0,%1,%2,%3};"
    : "+f"(c[0]),"+f"(c[1]),"+f"(c[2]),"+f"(c[3])
    : "r"(a[0]),"r"(a[1]),"r"(a[2]),"r"(a[3]),"r"(b[0]),"r"(b[1]));
}

// ---------------- diffusion GEMM (R10 config: proven optimum) ----------------
#define D_LDA 72
#define D_LDB 136
#define D_SA (128*D_LDA)
#define D_SB (64*D_LDB)
#define D_STAGES 3
#define D_SMEM (D_STAGES*(D_SA+D_SB)*2)   // 107,520 bytes

__global__ void __launch_bounds__(256,2) k_dgemm(
    const __half* __restrict__ A, const __half* __restrict__ Bm,
    float a0, float a1, const __half* __restrict__ subh,
    __half* __restrict__ Ch)
{
  extern __shared__ __half smh[];
  __half* sA = smh;
  __half* sB = smh + D_STAGES*D_SA;
  constexpr int BK=64, KT=NN/BK;

  const int tid=threadIdx.x, lane=tid&31, warp=tid>>5;
  const int wm=warp>>1, wn=warp&1;
  const int bm=blockIdx.y*128, bn=blockIdx.x*128;
  const float alpha = (bm<NN)? a0 : a1;
  const bool dosub = (subh!=nullptr) && (bm<NN);

  float acc[2][8][4];
  #pragma unroll
  for(int i=0;i<2;i++)
    #pragma unroll
    for(int j=0;j<8;j++)
      #pragma unroll
      for(int q=0;q<4;q++) acc[i][j][q]=0.f;

  auto loadA=[&](int st,int k0){
    __half* base=sA+st*D_SA;
    #pragma unroll
    for(int i=0;i<4;i++){
      int c=tid+i*256, r=c>>3, ch=c&7;
      cpa16(saddr(base+r*D_LDA+ch*8), A+(size_t)(bm+r)*NN+k0+ch*8);
    }
  };
  auto loadB=[&](int st,int k0){
    __half* base=sB+st*D_SB;
    #pragma unroll
    for(int i=0;i<4;i++){
      int c=tid+i*256, r=c>>4, ch=c&15;
      cpa16(saddr(base+r*D_LDB+ch*8), Bm+(size_t)(k0+r)*CC+bn+ch*8);
    }
  };

  loadA(0,0);    loadB(0,0);    cpcommit();
  loadA(1,BK);   loadB(1,BK);   cpcommit();

  int st=0;
  for(int kt=0;kt<KT;kt++){
    cpwait<1>();
    __syncthreads();
    const int lb=kt+2;
    if(lb<KT){
      int ls=lb%3;
      loadA(ls, lb*BK); loadB(ls, lb*BK);
    }
    cpcommit();
    const __half* a0p=sA+st*D_SA;
    const __half* b0p=sB+st*D_SB;
    st++; if(st==3) st=0;
    #pragma unroll
    for(int ks=0;ks<4;ks++){
      uint32_t af[2][4];
      #pragma unroll
      for(int mi=0;mi<2;mi++){
        int row=wm*32+mi*16+(lane&7)+((lane>>3)&1)*8;
        int col=ks*16+((lane>>4)&1)*8;
        ldsm4(af[mi], saddr(a0p+row*D_LDA+col));
      }
      uint32_t bf[8][2];
      #pragma unroll
      for(int nj=0;nj<4;nj++){
        int kr=ks*16+((lane>>3)&1)*8+(lane&7);
        int nc=wn*64+nj*16+((lane>>4)&1)*8;
        uint32_t t[4];
        ldsm4t(t, saddr(b0p+kr*D_LDB+nc));
        bf[2*nj][0]=t[0]; bf[2*nj][1]=t[1];
        bf[2*nj+1][0]=t[2]; bf[2*nj+1][1]=t[3];
      }
      #pragma unroll
      for(int mi=0;mi<2;mi++)
        #pragma unroll
        for(int nj=0;nj<8;nj++)
          mma16816(acc[mi][nj], af[mi], bf[nj]);
    }
  }

  #pragma unroll
  for(int mi=0;mi<2;mi++)
    #pragma unroll
    for(int nj=0;nj<8;nj++){
      int r0=bm+wm*32+mi*16+(lane>>2);
      int c0=bn+wn*64+nj*8+2*(lane&3);
      #pragma unroll
      for(int h=0;h<2;h++){
        int rr=r0+h*8;
        float v0=acc[mi][nj][2*h]*alpha;
        float v1=acc[mi][nj][2*h+1]*alpha;
        size_t idx=(size_t)rr*CC+c0;
        if(dosub){
          __half2 s=*(const __half2*)(subh+idx);
          v0-=__low2float(s); v1-=__high2float(s);
        }
        *(__half2*)(Ch+idx)=__floats2half2_rn(v0,v1);
      }
    }
}

// ---------------- output GEMM (BN=64, R10 structure) ----------------
// rows = (b, n): A[r, m*80+f] = Xbase[m][n, b*66+f] (f<66, else 0); B = W2 [400][64].
// EP1: gate[vr*64+cc] = sigmoid(acc + bias[cc])   (fp16)
// EP2: c=tanh(acc+bias); u=g_Uh[vr*64+cc]; out = u*hx+(1-u)*c
template<int EP>
__global__ void __launch_bounds__(256) k_ogemm(
    const __half* __restrict__ Xbase,
    const __half* __restrict__ W2,
    const float* __restrict__ bias,
    __half* __restrict__ gate,
    const float* __restrict__ hx, float* __restrict__ outp)
{
  constexpr int BN=64, BK=16, KT=25;
  constexpr int LDA_S=24, LDB_S=BN+8;
  constexpr int WN=BN/2, NF=WN/8;

  __shared__ __half sA[2][128*LDA_S];
  __shared__ __half sB[2][BK*LDB_S];

  const int tid=threadIdx.x, lane=tid&31, warp=tid>>5;
  const int wm=warp>>1, wn=warp&1;
  const int b=blockIdx.y>>5;
  const int n0=(blockIdx.y&31)<<7;
  const int boff=b*66;

  float acc[2][NF][4];
  #pragma unroll
  for(int i=0;i<2;i++)
    #pragma unroll
    for(int j=0;j<NF;j++)
      #pragma unroll
      for(int q=0;q<4;q++) acc[i][j][q]=0.f;

  auto loadA=[&](int st,int kt){
    const int m=kt/5, f0=(kt%5)*16;
    const __half* Xm=Xbase+(size_t)m*XSTR;
    #pragma unroll
    for(int i=0;i<4;i++){
      int c=tid+i*256, r=c>>3, w=c&7;
      int f=f0+w*2;
      int ok=(f<66);
      int fs=ok?f:0;
      cpa4z(saddr(&sA[st][r*LDA_S+w*2]),
            Xm+(size_t)(n0+r)*CC+boff+fs, ok?4:0);
    }
  };
  auto loadB=[&](int st,int k0){
    constexpr int CH=BN/8;
    if(tid<BK*CH){
      int r=tid/CH, ch=tid%CH;
      cpa16(saddr(&sB[st][r*LDB_S+ch*8]), W2+(size_t)(k0+r)*BN+ch*8);
    }
  };

  loadA(0,0); loadB(0,0); cpcommit();

  for(int kt=0;kt<KT;kt++){
    if(kt+1<KT){
      loadA((kt+1)&1,kt+1); loadB((kt+1)&1,(kt+1)*BK);
      cpcommit(); cpwait<1>();
    } else cpwait<0>();
    __syncthreads();
    const int st=kt&1;
    uint32_t af[2][4];
    #pragma unroll
    for(int mi=0;mi<2;mi++){
      int row=wm*32+mi*16+(lane&7)+((lane>>3)&1)*8;
      int col=((lane>>4)&1)*8;
      ldsm4(af[mi], saddr(&sA[st][row*LDA_S+col]));
    }
    uint32_t bf[NF][2];
    #pragma unroll
    for(int nj=0;nj<NF/2;nj++){
      int kr=((lane>>3)&1)*8+(lane&7);
      int nc=wn*WN+nj*16+((lane>>4)&1)*8;
      uint32_t t[4];
      ldsm4t(t, saddr(&sB[st][kr*LDB_S+nc]));
      bf[2*nj][0]=t[0]; bf[2*nj][1]=t[1];
      bf[2*nj+1][0]=t[2]; bf[2*nj+1][1]=t[3];
    }
    #pragma unroll
    for(int mi=0;mi<2;mi++)
      #pragma unroll
      for(int nj=0;nj<NF;nj++)
        mma16816(acc[mi][nj], af[mi], bf[nj]);
    __syncthreads();
  }

  #pragma unroll
  for(int mi=0;mi<2;mi++)
    #pragma unroll
    for(int nj=0;nj<NF;nj++){
      int rl0=wm*32+mi*16+(lane>>2);
      int c0=wn*WN+nj*8+2*(lane&3);
      #pragma unroll
      for(int q=0;q<4;q++){
        int n=n0+rl0+(q>>1)*8, cc=c0+(q&1);
        float v=acc[mi][nj][q];
        size_t vr=(size_t)b*NN+n;
        if(EP==1){
          float s=1.f/(1.f+expf(-(v+bias[cc])));
          gate[vr*64+cc]=__float2half(s);
        } else {
          float cg=tanhf(v+bias[cc]);
          float u=__half2float(g_Uh[vr*64+cc]);
          size_t oidx=vr*UNITS+cc;
          float h=hx[oidx];
          outp[oidx]=u*h+(1.f-u)*cg;
        }
      }
    }
}

// ---------------- glue ----------------
__global__ void k_conv_S(const float4* __restrict__ S4){
  size_t stride=(size_t)gridDim.x*blockDim.x;
  size_t tot=(size_t)2*NN*NN/4;
  for(size_t i=(size_t)blockIdx.x*blockDim.x+threadIdx.x; i<tot; i+=stride){
    float4 v=S4[i];
    __half2 a=__floats2half2_rn(v.x*SSCALE,v.y*SSCALE);
    __half2 b=__floats2half2_rn(v.z*SSCALE,v.w*SSCALE);
    uint2 o; o.x=*(uint32_t*)&a; o.y=*(uint32_t*)&b;
    *(uint2*)&g_S16[i*4]=o;
  }
}

// W2r[k][o]=wfn[(f*5+m)*128+o]; W2u[k][o]=wfn[(f*5+m)*128+64+o]; W2g[k][o]=wg[(f*5+m)*64+o]
__global__ void k_conv_W(const float* __restrict__ wfn, const float* __restrict__ wg){
  int i=blockIdx.x*blockDim.x+threadIdx.x;
  if(i<KOUT_K*64){
    int k=i>>6, o=i&63;
    int m=k/80, f=k%80;
    bool ok=(f<66);
    g_W2r[i]=ok?__float2half(wfn[(f*5+m)*128+o])    :__float2half(0.f);
    g_W2u[i]=ok?__float2half(wfn[(f*5+m)*128+64+o]) :__float2half(0.f);
    g_W2g[i]=ok?__float2half(wg[(f*5+m)*64+o])      :__float2half(0.f);
  }
}

// x0[n, b*66+f] = f<2 ? inputs[b, n*2+f] : state[b, n*64+(f-2)]
__global__ void k_pack(const float* __restrict__ inputs, const float* __restrict__ hx,
                       int use_r, __half* __restrict__ x0out)
{
  int n=blockIdx.x, tid=threadIdx.x;
  __shared__ float s[64][65];
  for(int i=tid;i<64*64;i+=256){
    int b=i>>6, j=i&63;
    float h=hx[(size_t)b*((size_t)NN*UNITS)+(size_t)n*64+j];
    if(use_r) h*=__half2float(g_Rh[((size_t)b*NN+n)*64+j]);
    s[j][b]=h;
  }
  __syncthreads();
  size_t base=(size_t)n*CC;
  for(int i=tid;i<CC;i+=256){
    int b=i/66, f=i-66*b;
    float v=(f<2)?inputs[(size_t)b*(NN*2)+n*2+f]:s[f-2][b];
    x0out[base+i]=__float2half(v);
  }
}

// ---------------- launcher ----------------
extern "C" void kernel_launch(void* const* d_in, const int* in_sizes, int n_in,
                              void* d_out, int out_size) {
  const float* inputs=(const float*)d_in[0];
  const float* hx    =(const float*)d_in[1];
  const float* sup   =(const float*)d_in[2];
  const float* wfn   =(const float*)d_in[3];
  const float* bfn   =(const float*)d_in[4];
  const float* wg    =(const float*)d_in[5];
  const float* bg    =(const float*)d_in[6];
  float* outp=(float*)d_out;

  cudaFuncSetAttribute(k_dgemm, cudaFuncAttributeMaxDynamicSharedMemorySize, D_SMEM);

  void *pS,*pXh,*pW2r,*pW2u,*pW2g,*pU,*pR;
  cudaGetSymbolAddress(&pS,g_S16);
  cudaGetSymbolAddress(&pXh,g_Xh);
  cudaGetSymbolAddress(&pW2r,g_W2r);
  cudaGetSymbolAddress(&pW2u,g_W2u);
  cudaGetSymbolAddress(&pW2g,g_W2g);
  cudaGetSymbolAddress(&pU,g_Uh);
  cudaGetSymbolAddress(&pR,g_Rh);
  __half* S16=(__half*)pS;
  __half* X0 =(__half*)pXh;              // set 0: 5 planes
  __half* X1 =X0 + 5*XSTR;               // set 1
  __half* W2r=(__half*)pW2r;
  __half* W2u=(__half*)pW2u;
  __half* W2g=(__half*)pW2g;
  __half* Uh =(__half*)pU;
  __half* Rh =(__half*)pR;

  const size_t SZ=(size_t)NN*NN;

  // side stream + events (created per call; never destroyed mid-capture)
  cudaStream_t s2;
  cudaStreamCreateWithFlags(&s2, cudaStreamNonBlocking);
  cudaEvent_t eFork, eConv, eX, eU;
  cudaEventCreateWithFlags(&eFork, cudaEventDisableTiming);
  cudaEventCreateWithFlags(&eConv, cudaEventDisableTiming);
  cudaEventCreateWithFlags(&eX,    cudaEventDisableTiming);
  cudaEventCreateWithFlags(&eU,    cudaEventDisableTiming);

  dim3 g1(CC/128, NN/128);       // (33, 32)  single support
  dim3 g23(CC/128, 2*NN/128);    // (33, 64)  fused S0|S1
  dim3 gOut(1, 2048);

  // fork: conversions on s2, pack0 on main (independent)
  cudaEventRecord(eFork, 0);
  cudaStreamWaitEvent(s2, eFork, 0);
  k_conv_S<<<2048,256,0,s2>>>((const float4*)sup);
  k_conv_W<<<(KOUT_K*64+255)/256,256,0,s2>>>(wfn,wg);
  cudaEventRecord(eConv, s2);

  k_pack<<<NN,256>>>(inputs,hx,0, X0);
  cudaStreamWaitEvent(0, eConv, 0);

  // round 0 diffusion chain (set 0)
  k_dgemm<<<g1,256,D_SMEM>>>(S16, X0, 1.f/SSCALE, 0.f, nullptr, X0+XSTR);
  k_dgemm<<<g23,256,D_SMEM>>>(S16, X0+XSTR, 2.f/SSCALE, 1.f/SSCALE, X0, X0+2*XSTR);
  k_dgemm<<<g1,256,D_SMEM>>>(S16+SZ, X0+3*XSTR, 2.f/SSCALE, 0.f, X0+XSTR, X0+4*XSTR);

  // u-gate GEMM on side stream: hidden under the entire round-1 chain
  cudaEventRecord(eX, 0);
  cudaStreamWaitEvent(s2, eX, 0);
  k_ogemm<1><<<gOut,256,0,s2>>>(X0, W2u, bfn+64, Uh, nullptr, nullptr);
  cudaEventRecord(eU, s2);

  // r-gate GEMM on main (needed immediately by pack1)
  k_ogemm<1><<<gOut,256>>>(X0, W2r, bfn, Rh, nullptr, nullptr);

  // round 1 (set 1)
  k_pack<<<NN,256>>>(inputs,hx,1, X1);
  k_dgemm<<<g1,256,D_SMEM>>>(S16, X1, 1.f/SSCALE, 0.f, nullptr, X1+XSTR);
  k_dgemm<<<g23,256,D_SMEM>>>(S16, X1+XSTR, 2.f/SSCALE, 1.f/SSCALE, X1, X1+2*XSTR);
  k_dgemm<<<g1,256,D_SMEM>>>(S16+SZ, X1+3*XSTR, 2.f/SSCALE, 0.f, X1+XSTR, X1+4*XSTR);

  // join u, then final EP2
  cudaStreamWaitEvent(0, eU, 0);
  k_ogemm<2><<<gOut,256>>>(X1, W2g, bg, nullptr, hx, outp);
}

// round 15
// speedup vs baseline: 1.7825x; 1.7825x over previous
#include <cuda_runtime.h>
#include <cuda_fp16.h>
#include <cstdint>

#define NN     4096
#define UNITS  64
#define CC     4224              // 64 batches * 66 features, col = b*66+f
#define BNROWS 262144
#define SSCALE 1024.0f
#define KOUT_K 400               // out-GEMM K: 5 m-segments * 80 (66 valid, pad 0)

// ---------------- scratch ----------------
__device__ __align__(256) __half g_S16[(size_t)2*NN*NN];     // supports fp16, x1024 (S0|S1)
__device__ __align__(256) __half g_Xh[5][(size_t)NN*CC];     // x0..x4 fp16
__device__ __align__(256) float  g_Value[(size_t)BNROWS*128];// sigmoid gates (r|u)
__device__ __align__(256) __half g_W2fn[KOUT_K*128];         // rearranged weights
__device__ __align__(256) __half g_W2g[KOUT_K*64];

// ---------------- helpers ----------------
__device__ __forceinline__ uint32_t saddr(const void* p){
  return (uint32_t)__cvta_generic_to_shared(p);
}
__device__ __forceinline__ void cpa16(uint32_t s, const void* g){
  asm volatile("cp.async.cg.shared.global [%0], [%1], 16;" :: "r"(s), "l"(g));
}
__device__ __forceinline__ void cpa4z(uint32_t s, const void* g, int srcsz){
  asm volatile("cp.async.ca.shared.global [%0], [%1], 4, %2;"
               :: "r"(s), "l"(g), "r"(srcsz));
}
__device__ __forceinline__ void cpcommit(){ asm volatile("cp.async.commit_group;"); }
template<int N_> __device__ __forceinline__ void cpwait(){
  asm volatile("cp.async.wait_group %0;" :: "n"(N_));
}
__device__ __forceinline__ void ldsm4(uint32_t* r, uint32_t a){
  asm volatile("ldmatrix.sync.aligned.m8n8.x4.shared.b16 {%0,%1,%2,%3}, [%4];"
    : "=r"(r[0]),"=r"(r[1]),"=r"(r[2]),"=r"(r[3]) : "r"(a));
}
__device__ __forceinline__ void ldsm4t(uint32_t* r, uint32_t a){
  asm volatile("ldmatrix.sync.aligned.m8n8.x4.trans.shared.b16 {%0,%1,%2,%3}, [%4];"
    : "=r"(r[0]),"=r"(r[1]),"=r"(r[2]),"=r"(r[3]) : "r"(a));
}
__device__ __forceinline__ void mma16816(float* c, const uint32_t* a, const uint32_t* b){
  asm volatile("mma.sync.aligned.m16n8k16.row.col.f32.f16.f16.f32 "
    "{%0,%1,%2,%3},{%4,%5,%6,%7},{%8,%9},{%0,%1,%2,%3};"
    : "+f"(c[0]),"+f"(c[1]),"+f"(c[2]),"+f"(c[3])
    : "r"(a[0]),"r"(a[1]),"r"(a[2]),"r"(a[3]),"r"(b[0]),"r"(b[1]));
}

// ---------------- diffusion GEMM ----------------
// C(M,4224) = alpha*(A@B) [- sub], M = 4096 (single support) or 8192 (fused S0|S1).
// alpha = bm<NN ? a0 : a1; subtract only when bm<NN and subh!=null.
// BM=128, BN=128, BK=64. 8 warps, warp tile 32x64. 3-stage, 1 sync/kt, 2 CTAs/SM.
#define D_LDA 72
#define D_LDB 136
#define D_SA (128*D_LDA)
#define D_SB (64*D_LDB)
#define D_STAGES 3
#define D_SMEM (D_STAGES*(D_SA+D_SB)*2)   // 107,520 bytes

__global__ void __launch_bounds__(256,2) k_dgemm(
    const __half* __restrict__ A, const __half* __restrict__ Bm,
    float a0, float a1, const __half* __restrict__ subh,
    __half* __restrict__ Ch)
{
  extern __shared__ __half smh[];
  __half* sA = smh;
  __half* sB = smh + D_STAGES*D_SA;
  constexpr int BK=64, KT=NN/BK;

  const int tid=threadIdx.x, lane=tid&31, warp=tid>>5;
  const int wm=warp>>1, wn=warp&1;
  const int bm=blockIdx.y*128, bn=blockIdx.x*128;
  const float alpha = (bm<NN)? a0 : a1;
  const bool dosub = (subh!=nullptr) && (bm<NN);

  float acc[2][8][4];
  #pragma unroll
  for(int i=0;i<2;i++)
    #pragma unroll
    for(int j=0;j<8;j++)
      #pragma unroll
      for(int q=0;q<4;q++) acc[i][j][q]=0.f;

  auto loadA=[&](int st,int k0){
    __half* base=sA+st*D_SA;
    #pragma unroll
    for(int i=0;i<4;i++){
      int c=tid+i*256, r=c>>3, ch=c&7;
      cpa16(saddr(base+r*D_LDA+ch*8), A+(size_t)(bm+r)*NN+k0+ch*8);
    }
  };
  auto loadB=[&](int st,int k0){
    __half* base=sB+st*D_SB;
    #pragma unroll
    for(int i=0;i<4;i++){
      int c=tid+i*256, r=c>>4, ch=c&15;
      cpa16(saddr(base+r*D_LDB+ch*8), Bm+(size_t)(k0+r)*CC+bn+ch*8);
    }
  };

  loadA(0,0);    loadB(0,0);    cpcommit();
  loadA(1,BK);   loadB(1,BK);   cpcommit();

  int st=0;
  for(int kt=0;kt<KT;kt++){
    cpwait<1>();
    __syncthreads();
    const int lb=kt+2;
    if(lb<KT){
      int ls=lb%3;
      loadA(ls, lb*BK); loadB(ls, lb*BK);
    }
    cpcommit();
    const __half* a0p=sA+st*D_SA;
    const __half* b0p=sB+st*D_SB;
    st++; if(st==3) st=0;
    #pragma unroll
    for(int ks=0;ks<4;ks++){
      uint32_t af[2][4];
      #pragma unroll
      for(int mi=0;mi<2;mi++){
        int row=wm*32+mi*16+(lane&7)+((lane>>3)&1)*8;
        int col=ks*16+((lane>>4)&1)*8;
        ldsm4(af[mi], saddr(a0p+row*D_LDA+col));
      }
      uint32_t bf[8][2];
      #pragma unroll
      for(int nj=0;nj<4;nj++){
        int kr=ks*16+((lane>>3)&1)*8+(lane&7);
        int nc=wn*64+nj*16+((lane>>4)&1)*8;
        uint32_t t[4];
        ldsm4t(t, saddr(b0p+kr*D_LDB+nc));
        bf[2*nj][0]=t[0]; bf[2*nj][1]=t[1];
        bf[2*nj+1][0]=t[2]; bf[2*nj+1][1]=t[3];
      }
      #pragma unroll
      for(int mi=0;mi<2;mi++)
        #pragma unroll
        for(int nj=0;nj<8;nj++)
          mma16816(acc[mi][nj], af[mi], bf[nj]);
    }
  }

  #pragma unroll
  for(int mi=0;mi<2;mi++)
    #pragma unroll
    for(int nj=0;nj<8;nj++){
      int r0=bm+wm*32+mi*16+(lane>>2);
      int c0=bn+wn*64+nj*8+2*(lane&3);
      #pragma unroll
      for(int h=0;h<2;h++){
        int rr=r0+h*8;
        float v0=acc[mi][nj][2*h]*alpha;
        float v1=acc[mi][nj][2*h+1]*alpha;
        size_t idx=(size_t)rr*CC+c0;
        if(dosub){
          __half2 s=*(const __half2*)(subh+idx);
          v0-=__low2float(s); v1-=__high2float(s);
        }
        *(__half2*)(Ch+idx)=__floats2half2_rn(v0,v1);
      }
    }
}

// ---------------- output GEMM ----------------
// rows = (b, n): A[r, m*80+f] = x_m[n, b*66+f] (f<66, else 0); B = g_W2*.
// EP1: g_Value[(b*NN+n)*128+cc] = sigmoid(acc+bias)
// EP2: c=tanh(acc+bias); u=Value[..64+cc]; out = u*hx+(1-u)*c
template<int BN, int EP>
__global__ void __launch_bounds__(256) k_ogemm(
    const __half* __restrict__ W2,
    const float* __restrict__ bias,
    const float* __restrict__ hx, float* __restrict__ outp)
{
  constexpr int BK=16, KT=25;
  constexpr int LDA_S=24, LDB_S=BN+8;
  constexpr int WN=BN/2, NF=WN/8;

  __shared__ __half sA[2][128*LDA_S];
  __shared__ __half sB[2][BK*LDB_S];

  const int tid=threadIdx.x, lane=tid&31, warp=tid>>5;
  const int wm=warp>>1, wn=warp&1;
  const int b=blockIdx.y>>5;
  const int n0=(blockIdx.y&31)<<7;
  const int boff=b*66;

  float acc[2][NF][4];
  #pragma unroll
  for(int i=0;i<2;i++)
    #pragma unroll
    for(int j=0;j<NF;j++)
      #pragma unroll
      for(int q=0;q<4;q++) acc[i][j][q]=0.f;

  // A: 4-byte cp.async (global addr only 4B-aligned: b*66 offset), zfill f>=66
  auto loadA=[&](int st,int kt){
    const int m=kt/5, f0=(kt%5)*16;
    const __half* Xm=g_Xh[m];
    #pragma unroll
    for(int i=0;i<4;i++){
      int c=tid+i*256, r=c>>3, w=c&7;
      int f=f0+w*2;
      int ok=(f<66);
      int fs=ok?f:0;
      cpa4z(saddr(&sA[st][r*LDA_S+w*2]),
            Xm+(size_t)(n0+r)*CC+boff+fs, ok?4:0);
    }
  };
  auto loadB=[&](int st,int k0){
    constexpr int CH=BN/8;
    if(tid<BK*CH){
      int r=tid/CH, ch=tid%CH;
      cpa16(saddr(&sB[st][r*LDB_S+ch*8]), W2+(size_t)(k0+r)*BN+ch*8);
    }
  };

  loadA(0,0); loadB(0,0); cpcommit();

  for(int kt=0;kt<KT;kt++){
    if(kt+1<KT){
      loadA((kt+1)&1,kt+1); loadB((kt+1)&1,(kt+1)*BK);
      cpcommit(); cpwait<1>();
    } else cpwait<0>();
    __syncthreads();
    const int st=kt&1;
    uint32_t af[2][4];
    #pragma unroll
    for(int mi=0;mi<2;mi++){
      int row=wm*32+mi*16+(lane&7)+((lane>>3)&1)*8;
      int col=((lane>>4)&1)*8;
      ldsm4(af[mi], saddr(&sA[st][row*LDA_S+col]));
    }
    uint32_t bf[NF][2];
    #pragma unroll
    for(int nj=0;nj<NF/2;nj++){
      int kr=((lane>>3)&1)*8+(lane&7);
      int nc=wn*WN+nj*16+((lane>>4)&1)*8;
      uint32_t t[4];
      ldsm4t(t, saddr(&sB[st][kr*LDB_S+nc]));
      bf[2*nj][0]=t[0]; bf[2*nj][1]=t[1];
      bf[2*nj+1][0]=t[2]; bf[2*nj+1][1]=t[3];
    }
    #pragma unroll
    for(int mi=0;mi<2;mi++)
      #pragma unroll
      for(int nj=0;nj<NF;nj++)
        mma16816(acc[mi][nj], af[mi], bf[nj]);
    __syncthreads();
  }

  #pragma unroll
  for(int mi=0;mi<2;mi++)
    #pragma unroll
    for(int nj=0;nj<NF;nj++){
      int rl0=wm*32+mi*16+(lane>>2);
      int c0=wn*WN+nj*8+2*(lane&3);
      #pragma unroll
      for(int q=0;q<4;q++){
        int n=n0+rl0+(q>>1)*8, cc=c0+(q&1);
        float v=acc[mi][nj][q];
        size_t vr=(size_t)b*NN+n;
        if(EP==1){
          g_Value[vr*128+cc]=1.f/(1.f+expf(-(v+bias[cc])));
        } else {
          float cg=tanhf(v+bias[cc]);
          float u=g_Value[vr*128+64+cc];
          size_t oidx=vr*UNITS+cc;
          float h=hx[oidx];
          outp[oidx]=u*h+(1.f-u)*cg;
        }
      }
    }
}

// ---------------- glue ----------------
__global__ void k_conv_S(const float4* __restrict__ S4){
  size_t stride=(size_t)gridDim.x*blockDim.x;
  size_t tot=(size_t)2*NN*NN/4;
  for(size_t i=(size_t)blockIdx.x*blockDim.x+threadIdx.x; i<tot; i+=stride){
    float4 v=S4[i];
    __half2 a=__floats2half2_rn(v.x*SSCALE,v.y*SSCALE);
    __half2 b=__floats2half2_rn(v.z*SSCALE,v.w*SSCALE);
    uint2 o; o.x=*(uint32_t*)&a; o.y=*(uint32_t*)&b;
    *(uint2*)&g_S16[i*4]=o;
  }
}

// rearrange weights: g_W2[m*80+f][o] = w[(f*5+m)*ld+o], zero for f>=66
__global__ void k_conv_W(const float* __restrict__ wfn, const float* __restrict__ wg){
  int i=blockIdx.x*blockDim.x+threadIdx.x;
  if(i<KOUT_K*128){
    int k=i>>7, o=i&127;
    int m=k/80, f=k%80;
    g_W2fn[i]=(f<66)?__float2half(wfn[(f*5+m)*128+o]):__float2half(0.f);
  }
  if(i<KOUT_K*64){
    int k=i>>6, o=i&63;
    int m=k/80, f=k%80;
    g_W2g[i]=(f<66)?__float2half(wg[(f*5+m)*64+o]):__float2half(0.f);
  }
}

// x0[n, b*66+f] = f<2 ? inputs[b, n*2+f] : state[b, n*64+(f-2)]
__global__ void k_pack(const float* __restrict__ inputs, const float* __restrict__ hx,
                       int use_r)
{
  int n=blockIdx.x, tid=threadIdx.x;
  __shared__ float s[64][65];
  for(int i=tid;i<64*64;i+=256){
    int b=i>>6, j=i&63;
    float h=hx[(size_t)b*((size_t)NN*UNITS)+(size_t)n*64+j];
    if(use_r) h*=g_Value[((size_t)b*NN+n)*128+j];
    s[j][b]=h;
  }
  __syncthreads();
  size_t base=(size_t)n*CC;
  for(int i=tid;i<CC;i+=256){
    int b=i/66, f=i-66*b;
    float v=(f<2)?inputs[(size_t)b*(NN*2)+n*2+f]:s[f-2][b];
    g_Xh[0][base+i]=__float2half(v);
  }
}

// ---------------- launcher ----------------
extern "C" void kernel_launch(void* const* d_in, const int* in_sizes, int n_in,
                              void* d_out, int out_size) {
  const float* inputs=(const float*)d_in[0];
  const float* hx    =(const float*)d_in[1];
  const float* sup   =(const float*)d_in[2];
  const float* wfn   =(const float*)d_in[3];
  const float* bfn   =(const float*)d_in[4];
  const float* wg    =(const float*)d_in[5];
  const float* bg    =(const float*)d_in[6];
  float* outp=(float*)d_out;

  cudaFuncSetAttribute(k_dgemm, cudaFuncAttributeMaxDynamicSharedMemorySize, D_SMEM);

  void *pS,*pXh,*pWfn,*pWg;
  cudaGetSymbolAddress(&pS,g_S16);
  cudaGetSymbolAddress(&pXh,g_Xh);
  cudaGetSymbolAddress(&pWfn,g_W2fn);
  cudaGetSymbolAddress(&pWg,g_W2g);
  __half* S16=(__half*)pS;
  __half* Xh =(__half*)pXh;
  __half* Wfn=(__half*)pWfn;
  __half* Wg =(__half*)pWg;

  const size_t NC=(size_t)NN*CC;
  const size_t SZ=(size_t)NN*NN;

  k_conv_S<<<2048,256>>>((const float4*)sup);
  k_conv_W<<<(KOUT_K*128+255)/256,256>>>(wfn,wg);

  dim3 g1(CC/128, NN/128);       // (33, 32)  single support
  dim3 g23(CC/128, 2*NN/128);    // (33, 64)  fused S0|S1
  dim3 gOut(1, 2048);

  for(int round=0;round<2;round++){
    k_pack<<<NN,256>>>(inputs,hx,round);

    // x1 = (S0 @ x0)/1024                          -> Xh[1]
    k_dgemm<<<g1,256,D_SMEM>>>(S16, Xh, 1.f/SSCALE, 0.f, nullptr, Xh+NC);
    // fused: x2 = 2*(S0@x1) - x0  (rows < 4096)    -> Xh[2]
    //        x3 = (S1@x1)/1024    (rows >= 4096)   -> Xh[3]
    k_dgemm<<<g23,256,D_SMEM>>>(S16, Xh+NC, 2.f/SSCALE, 1.f/SSCALE, Xh, Xh+2*NC);
    // x4 = 2*(S1 @ x3) - x1                        -> Xh[4]
    k_dgemm<<<g1,256,D_SMEM>>>(S16+SZ, Xh+3*NC, 2.f/SSCALE, 0.f, Xh+NC, Xh+4*NC);

    if(round==0){
      k_ogemm<128,1><<<gOut,256>>>(Wfn, bfn, nullptr, nullptr);
    } else {
      k_ogemm<64,2><<<gOut,256>>>(Wg, bg, hx, outp);
    }
  }
}

// round 16
// speedup vs baseline: 1.7839x; 1.0008x over previous
#include <cuda_runtime.h>
#include <cuda_fp16.h>
#include <cstdint>

#define NN     4096
#define UNITS  64
#define CC     4224              // 64 batches * 66 features, col = b*66+f
#define BNROWS 262144
#define SSCALE 1024.0f
#define KOUT_K 400               // out-GEMM K: 5 m-segments * 80 (66 valid, pad 0)
#define XSTR   ((size_t)NN*CC)

// ---------------- scratch ----------------
__device__ __align__(256) __half g_S16[(size_t)2*NN*NN];     // supports fp16, x1024 (S0|S1)
__device__ __align__(256) __half g_Xh[6][XSTR];              // planes: 0=x0(r0),1..4=x1..x4,5=x0(r1)
__device__ __align__(256) float  g_Value[(size_t)BNROWS*64]; // u gate (fp32, compact)
__device__ __align__(256) __half g_W2fn[KOUT_K*128];         // rearranged weights (r|u)
__device__ __align__(256) __half g_W2g[KOUT_K*64];

// ---------------- helpers ----------------
__device__ __forceinline__ uint32_t saddr(const void* p){
  return (uint32_t)__cvta_generic_to_shared(p);
}
__device__ __forceinline__ void cpa16(uint32_t s, const void* g){
  asm volatile("cp.async.cg.shared.global [%0], [%1], 16;" :: "r"(s), "l"(g));
}
__device__ __forceinline__ void cpa4z(uint32_t s, const void* g, int srcsz){
  asm volatile("cp.async.ca.shared.global [%0], [%1], 4, %2;"
               :: "r"(s), "l"(g), "r"(srcsz));
}
__device__ __forceinline__ void cpcommit(){ asm volatile("cp.async.commit_group;"); }
template<int N_> __device__ __forceinline__ void cpwait(){
  asm volatile("cp.async.wait_group %0;" :: "n"(N_));
}
__device__ __forceinline__ void ldsm4(uint32_t* r, uint32_t a){
  asm volatile("ldmatrix.sync.aligned.m8n8.x4.shared.b16 {%0,%1,%2,%3}, [%4];"
    : "=r"(r[0]),"=r"(r[1]),"=r"(r[2]),"=r"(r[3]) : "r"(a));
}
__device__ __forceinline__ void ldsm4t(uint32_t* r, uint32_t a){
  asm volatile("ldmatrix.sync.aligned.m8n8.x4.trans.shared.b16 {%0,%1,%2,%3}, [%4];"
    : "=r"(r[0]),"=r"(r[1]),"=r"(r[2]),"=r"(r[3]) : "r"(a));
}
__device__ __forceinline__ void mma16816(float* c, const uint32_t* a, const uint32_t* b){
  asm volatile("mma.sync.aligned.m16n8k16.row.col.f32.f16.f16.f32 "
    "{%0,%1,%2,%3},{%4,%5,%6,%7},{%8,%9},{%0,%1,%2,%3};"
    : "+f"(c[0]),"+f"(c[1]),"+f"(c[2]),"+f"(c[3])
    : "r"(a[0]),"r"(a[1]),"r"(a[2]),"r"(a[3]),"r"(b[0]),"r"(b[1]));
}

// ---------------- diffusion GEMM (R10 config: proven optimum) ----------------
// C(M,4224) = alpha*(A@B) [- sub], M = 4096 (single support) or 8192 (fused S0|S1).
// alpha = bm<NN ? a0 : a1; subtract only when bm<NN and subh!=null.
// BM=128, BN=128, BK=64. 8 warps, warp tile 32x64. 3-stage, 1 sync/kt, 2 CTAs/SM.
#define D_LDA 72
#define D_LDB 136
#define D_SA (128*D_LDA)
#define D_SB (64*D_LDB)
#define D_STAGES 3
#define D_SMEM (D_STAGES*(D_SA+D_SB)*2)   // 107,520 bytes

__global__ void __launch_bounds__(256,2) k_dgemm(
    const __half* __restrict__ A, const __half* __restrict__ Bm,
    float a0, float a1, const __half* __restrict__ subh,
    __half* __restrict__ Ch)
{
  extern __shared__ __half smh[];
  __half* sA = smh;
  __half* sB = smh + D_STAGES*D_SA;
  constexpr int BK=64, KT=NN/BK;

  const int tid=threadIdx.x, lane=tid&31, warp=tid>>5;
  const int wm=warp>>1, wn=warp&1;
  const int bm=blockIdx.y*128, bn=blockIdx.x*128;
  const float alpha = (bm<NN)? a0 : a1;
  const bool dosub = (subh!=nullptr) && (bm<NN);

  float acc[2][8][4];
  #pragma unroll
  for(int i=0;i<2;i++)
    #pragma unroll
    for(int j=0;j<8;j++)
      #pragma unroll
      for(int q=0;q<4;q++) acc[i][j][q]=0.f;

  auto loadA=[&](int st,int k0){
    __half* base=sA+st*D_SA;
    #pragma unroll
    for(int i=0;i<4;i++){
      int c=tid+i*256, r=c>>3, ch=c&7;
      cpa16(saddr(base+r*D_LDA+ch*8), A+(size_t)(bm+r)*NN+k0+ch*8);
    }
  };
  auto loadB=[&](int st,int k0){
    __half* base=sB+st*D_SB;
    #pragma unroll
    for(int i=0;i<4;i++){
      int c=tid+i*256, r=c>>4, ch=c&15;
      cpa16(saddr(base+r*D_LDB+ch*8), Bm+(size_t)(k0+r)*CC+bn+ch*8);
    }
  };

  loadA(0,0);    loadB(0,0);    cpcommit();
  loadA(1,BK);   loadB(1,BK);   cpcommit();

  int st=0;
  for(int kt=0;kt<KT;kt++){
    cpwait<1>();
    __syncthreads();
    const int lb=kt+2;
    if(lb<KT){
      int ls=lb%3;
      loadA(ls, lb*BK); loadB(ls, lb*BK);
    }
    cpcommit();
    const __half* a0p=sA+st*D_SA;
    const __half* b0p=sB+st*D_SB;
    st++; if(st==3) st=0;
    #pragma unroll
    for(int ks=0;ks<4;ks++){
      uint32_t af[2][4];
      #pragma unroll
      for(int mi=0;mi<2;mi++){
        int row=wm*32+mi*16+(lane&7)+((lane>>3)&1)*8;
        int col=ks*16+((lane>>4)&1)*8;
        ldsm4(af[mi], saddr(a0p+row*D_LDA+col));
      }
      uint32_t bf[8][2];
      #pragma unroll
      for(int nj=0;nj<4;nj++){
        int kr=ks*16+((lane>>3)&1)*8+(lane&7);
        int nc=wn*64+nj*16+((lane>>4)&1)*8;
        uint32_t t[4];
        ldsm4t(t, saddr(b0p+kr*D_LDB+nc));
        bf[2*nj][0]=t[0]; bf[2*nj][1]=t[1];
        bf[2*nj+1][0]=t[2]; bf[2*nj+1][1]=t[3];
      }
      #pragma unroll
      for(int mi=0;mi<2;mi++)
        #pragma unroll
        for(int nj=0;nj<8;nj++)
          mma16816(acc[mi][nj], af[mi], bf[nj]);
    }
  }

  #pragma unroll
  for(int mi=0;mi<2;mi++)
    #pragma unroll
    for(int nj=0;nj<8;nj++){
      int r0=bm+wm*32+mi*16+(lane>>2);
      int c0=bn+wn*64+nj*8+2*(lane&3);
      #pragma unroll
      for(int h=0;h<2;h++){
        int rr=r0+h*8;
        float v0=acc[mi][nj][2*h]*alpha;
        float v1=acc[mi][nj][2*h+1]*alpha;
        size_t idx=(size_t)rr*CC+c0;
        if(dosub){
          __half2 s=*(const __half2*)(subh+idx);
          v0-=__low2float(s); v1-=__high2float(s);
        }
        *(__half2*)(Ch+idx)=__floats2half2_rn(v0,v1);
      }
    }
}

// ---------------- output GEMM ----------------
// rows = (b, n): A[r, m*80+f] = Xm[n, b*66+f] (f<66, else 0); m=0 plane = x0r param.
// EP1: s=sigmoid(acc+bias); cc<64: x0w[n*CC+b*66+2+cc]=half(s*hx) (round-1 x0 state);
//      cc>=64: g_Value[vr*64+cc-64]=s (u gate)
// EP2: c=tanh(acc+bias); u=g_Value[vr*64+cc]; out = u*hx+(1-u)*c
template<int BN, int EP>
__global__ void __launch_bounds__(256) k_ogemm(
    const __half* __restrict__ x0r, __half* __restrict__ x0w,
    const __half* __restrict__ W2,
    const float* __restrict__ bias,
    const float* __restrict__ hx, float* __restrict__ outp)
{
  constexpr int BK=16, KT=25;
  constexpr int LDA_S=24, LDB_S=BN+8;
  constexpr int WN=BN/2, NF=WN/8;

  __shared__ __half sA[2][128*LDA_S];
  __shared__ __half sB[2][BK*LDB_S];

  const int tid=threadIdx.x, lane=tid&31, warp=tid>>5;
  const int wm=warp>>1, wn=warp&1;
  const int b=blockIdx.y>>5;
  const int n0=(blockIdx.y&31)<<7;
  const int boff=b*66;

  float acc[2][NF][4];
  #pragma unroll
  for(int i=0;i<2;i++)
    #pragma unroll
    for(int j=0;j<NF;j++)
      #pragma unroll
      for(int q=0;q<4;q++) acc[i][j][q]=0.f;

  // A: 4-byte cp.async (global addr only 4B-aligned: b*66 offset), zfill f>=66
  auto loadA=[&](int st,int kt){
    const int m=kt/5, f0=(kt%5)*16;
    const __half* Xm = (m==0)? x0r : g_Xh[m];
    #pragma unroll
    for(int i=0;i<4;i++){
      int c=tid+i*256, r=c>>3, w=c&7;
      int f=f0+w*2;
      int ok=(f<66);
      int fs=ok?f:0;
      cpa4z(saddr(&sA[st][r*LDA_S+w*2]),
            Xm+(size_t)(n0+r)*CC+boff+fs, ok?4:0);
    }
  };
  auto loadB=[&](int st,int k0){
    constexpr int CH=BN/8;
    if(tid<BK*CH){
      int r=tid/CH, ch=tid%CH;
      cpa16(saddr(&sB[st][r*LDB_S+ch*8]), W2+(size_t)(k0+r)*BN+ch*8);
    }
  };

  loadA(0,0); loadB(0,0); cpcommit();

  for(int kt=0;kt<KT;kt++){
    if(kt+1<KT){
      loadA((kt+1)&1,kt+1); loadB((kt+1)&1,(kt+1)*BK);
      cpcommit(); cpwait<1>();
    } else cpwait<0>();
    __syncthreads();
    const int st=kt&1;
    uint32_t af[2][4];
    #pragma unroll
    for(int mi=0;mi<2;mi++){
      int row=wm*32+mi*16+(lane&7)+((lane>>3)&1)*8;
      int col=((lane>>4)&1)*8;
      ldsm4(af[mi], saddr(&sA[st][row*LDA_S+col]));
    }
    uint32_t bf[NF][2];
    #pragma unroll
    for(int nj=0;nj<NF/2;nj++){
      int kr=((lane>>3)&1)*8+(lane&7);
      int nc=wn*WN+nj*16+((lane>>4)&1)*8;
      uint32_t t[4];
      ldsm4t(t, saddr(&sB[st][kr*LDB_S+nc]));
      bf[2*nj][0]=t[0]; bf[2*nj][1]=t[1];
      bf[2*nj+1][0]=t[2]; bf[2*nj+1][1]=t[3];
    }
    #pragma unroll
    for(int mi=0;mi<2;mi++)
      #pragma unroll
      for(int nj=0;nj<NF;nj++)
        mma16816(acc[mi][nj], af[mi], bf[nj]);
    __syncthreads();
  }

  #pragma unroll
  for(int mi=0;mi<2;mi++)
    #pragma unroll
    for(int nj=0;nj<NF;nj++){
      int rl0=wm*32+mi*16+(lane>>2);
      int c0=wn*WN+nj*8+2*(lane&3);
      #pragma unroll
      for(int q=0;q<4;q++){
        int n=n0+rl0+(q>>1)*8, cc=c0+(q&1);
        float v=acc[mi][nj][q];
        size_t vr=(size_t)b*NN+n;
        if(EP==1){
          float s=1.f/(1.f+expf(-(v+bias[cc])));
          if(cc<64){
            float h=hx[vr*UNITS+cc];
            x0w[(size_t)n*CC + boff + 2 + cc] = __float2half(s*h);
          } else {
            g_Value[vr*64+(cc-64)]=s;
          }
        } else {
          float cg=tanhf(v+bias[cc]);
          float u=g_Value[vr*64+cc];
          size_t oidx=vr*UNITS+cc;
          float h=hx[oidx];
          outp[oidx]=u*h+(1.f-u)*cg;
        }
      }
    }
}

// ---------------- glue ----------------
__global__ void k_conv_S(const float4* __restrict__ S4){
  size_t stride=(size_t)gridDim.x*blockDim.x;
  size_t tot=(size_t)2*NN*NN/4;
  for(size_t i=(size_t)blockIdx.x*blockDim.x+threadIdx.x; i<tot; i+=stride){
    float4 v=S4[i];
    __half2 a=__floats2half2_rn(v.x*SSCALE,v.y*SSCALE);
    __half2 b=__floats2half2_rn(v.z*SSCALE,v.w*SSCALE);
    uint2 o; o.x=*(uint32_t*)&a; o.y=*(uint32_t*)&b;
    *(uint2*)&g_S16[i*4]=o;
  }
}

// rearrange weights: g_W2[m*80+f][o] = w[(f*5+m)*ld+o], zero for f>=66
__global__ void k_conv_W(const float* __restrict__ wfn, const float* __restrict__ wg){
  int i=blockIdx.x*blockDim.x+threadIdx.x;
  if(i<KOUT_K*128){
    int k=i>>7, o=i&127;
    int m=k/80, f=k%80;
    g_W2fn[i]=(f<66)?__float2half(wfn[(f*5+m)*128+o]):__float2half(0.f);
  }
  if(i<KOUT_K*64){
    int k=i>>6, o=i&63;
    int m=k/80, f=k%80;
    g_W2g[i]=(f<66)?__float2half(wg[(f*5+m)*64+o]):__float2half(0.f);
  }
}

// round-0 pack: x0a full (inputs+hx); x0b inputs cols only (state cols written by EP1)
__global__ void k_pack(const float* __restrict__ inputs, const float* __restrict__ hx,
                       __half* __restrict__ x0a, __half* __restrict__ x0b)
{
  int n=blockIdx.x, tid=threadIdx.x;
  __shared__ float s[64][65];
  for(int i=tid;i<64*64;i+=256){
    int b=i>>6, j=i&63;
    s[j][b]=hx[(size_t)b*((size_t)NN*UNITS)+(size_t)n*64+j];
  }
  __syncthreads();
  size_t base=(size_t)n*CC;
  for(int i=tid;i<CC;i+=256){
    int b=i/66, f=i-66*b;
    float v=(f<2)?inputs[(size_t)b*(NN*2)+n*2+f]:s[f-2][b];
    __half hv=__float2half(v);
    x0a[base+i]=hv;
    if(f<2) x0b[base+i]=hv;
  }
}

// ---------------- launcher ----------------
extern "C" void kernel_launch(void* const* d_in, const int* in_sizes, int n_in,
                              void* d_out, int out_size) {
  const float* inputs=(const float*)d_in[0];
  const float* hx    =(const float*)d_in[1];
  const float* sup   =(const float*)d_in[2];
  const float* wfn   =(const float*)d_in[3];
  const float* bfn   =(const float*)d_in[4];
  const float* wg    =(const float*)d_in[5];
  const float* bg    =(const float*)d_in[6];
  float* outp=(float*)d_out;

  cudaFuncSetAttribute(k_dgemm, cudaFuncAttributeMaxDynamicSharedMemorySize, D_SMEM);

  void *pS,*pXh,*pWfn,*pWg;
  cudaGetSymbolAddress(&pS,g_S16);
  cudaGetSymbolAddress(&pXh,g_Xh);
  cudaGetSymbolAddress(&pWfn,g_W2fn);
  cudaGetSymbolAddress(&pWg,g_W2g);
  __half* S16=(__half*)pS;
  __half* Xh =(__half*)pXh;
  __half* Wfn=(__half*)pWfn;
  __half* Wg =(__half*)pWg;

  __half* P0=Xh;                 // x0 round 0
  __half* P1=Xh+1*XSTR;
  __half* P3=Xh+3*XSTR;
  __half* P5=Xh+5*XSTR;          // x0 round 1 (inputs prefilled; state from EP1)

  const size_t SZ=(size_t)NN*NN;

  k_conv_S<<<2048,256>>>((const float4*)sup);
  k_conv_W<<<(KOUT_K*128+255)/256,256>>>(wfn,wg);

  dim3 g1(CC/128, NN/128);       // (33, 32)  single support
  dim3 g23(CC/128, 2*NN/128);    // (33, 64)  fused S0|S1
  dim3 gOut(1, 2048);

  k_pack<<<NN,256>>>(inputs,hx, P0, P5);

  // round 0 (x0 = P0)
  k_dgemm<<<g1,256,D_SMEM>>>(S16, P0, 1.f/SSCALE, 0.f, nullptr, P1);
  k_dgemm<<<g23,256,D_SMEM>>>(S16, P1, 2.f/SSCALE, 1.f/SSCALE, P0, Xh+2*XSTR);
  k_dgemm<<<g1,256,D_SMEM>>>(S16+SZ, P3, 2.f/SSCALE, 0.f, P1, Xh+4*XSTR);
  // EP1: gates; writes r*hx -> P5 state cols, u -> g_Value
  k_ogemm<128,1><<<gOut,256>>>(P0, P5, Wfn, bfn, hx, nullptr);

  // round 1 (x0 = P5)
  k_dgemm<<<g1,256,D_SMEM>>>(S16, P5, 1.f/SSCALE, 0.f, nullptr, P1);
  k_dgemm<<<g23,256,D_SMEM>>>(S16, P1, 2.f/SSCALE, 1.f/SSCALE, P5, Xh+2*XSTR);
  k_dgemm<<<g1,256,D_SMEM>>>(S16+SZ, P3, 2.f/SSCALE, 0.f, P1, Xh+4*XSTR);
  // EP2: final GRU combine
  k_ogemm<64,2><<<gOut,256>>>(P5, nullptr, Wg, bg, hx, outp);
}

// round 17
// speedup vs baseline: 1.7852x; 1.0007x over previous
#include <cuda_runtime.h>
#include <cuda_fp16.h>
#include <cstdint>

#define NN     4096
#define UNITS  64
#define CC     4224              // 64 batches * 66 features, col = b*66+f
#define BNROWS 262144
#define SSCALE 1024.0f
#define KOUT_K 400               // out-GEMM K: 5 m-segments * 80 (66 valid, pad 0)
#define XSTR   ((size_t)NN*CC)

// ---------------- scratch ----------------
__device__ __align__(256) __half g_S16[(size_t)2*NN*NN];     // supports fp16, x1024 (S0|S1)
__device__ __align__(256) __half g_Xh[6][XSTR];              // planes: 0=x0(r0),1..4=x1..x4,5=x0(r1)
__device__ __align__(256) float  g_Value[(size_t)BNROWS*64]; // u gate (fp32, compact)
__device__ __align__(256) __half g_W2fn[KOUT_K*128];         // rearranged weights (r|u)
__device__ __align__(256) __half g_W2g[KOUT_K*64];

// ---------------- helpers ----------------
__device__ __forceinline__ uint32_t saddr(const void* p){
  return (uint32_t)__cvta_generic_to_shared(p);
}
__device__ __forceinline__ void cpa16(uint32_t s, const void* g){
  asm volatile("cp.async.cg.shared.global [%0], [%1], 16;" :: "r"(s), "l"(g));
}
__device__ __forceinline__ void cpa4z(uint32_t s, const void* g, int srcsz){
  asm volatile("cp.async.ca.shared.global [%0], [%1], 4, %2;"
               :: "r"(s), "l"(g), "r"(srcsz));
}
__device__ __forceinline__ void cpcommit(){ asm volatile("cp.async.commit_group;"); }
template<int N_> __device__ __forceinline__ void cpwait(){
  asm volatile("cp.async.wait_group %0;" :: "n"(N_));
}
__device__ __forceinline__ void ldsm4(uint32_t* r, uint32_t a){
  asm volatile("ldmatrix.sync.aligned.m8n8.x4.shared.b16 {%0,%1,%2,%3}, [%4];"
    : "=r"(r[0]),"=r"(r[1]),"=r"(r[2]),"=r"(r[3]) : "r"(a));
}
__device__ __forceinline__ void ldsm4t(uint32_t* r, uint32_t a){
  asm volatile("ldmatrix.sync.aligned.m8n8.x4.trans.shared.b16 {%0,%1,%2,%3}, [%4];"
    : "=r"(r[0]),"=r"(r[1]),"=r"(r[2]),"=r"(r[3]) : "r"(a));
}
__device__ __forceinline__ void mma16816(float* c, const uint32_t* a, const uint32_t* b){
  asm volatile("mma.sync.aligned.m16n8k16.row.col.f32.f16.f16.f32 "
    "{%0,%1,%2,%3},{%4,%5,%6,%7},{%8,%9},{%0,%1,%2,%3};"
    : "+f"(c[0]),"+f"(c[1]),"+f"(c[2]),"+f"(c[3])
    : "r"(a[0]),"r"(a[1]),"r"(a[2]),"r"(a[3]),"r"(b[0]),"r"(b[1]));
}

// ---------------- diffusion GEMM (R10 config: proven optimum) ----------------
#define D_LDA 72
#define D_LDB 136
#define D_SA (128*D_LDA)
#define D_SB (64*D_LDB)
#define D_STAGES 3
#define D_SMEM (D_STAGES*(D_SA+D_SB)*2)   // 107,520 bytes

__global__ void __launch_bounds__(256,2) k_dgemm(
    const __half* __restrict__ A, const __half* __restrict__ Bm,
    float a0, float a1, const __half* __restrict__ subh,
    __half* __restrict__ Ch)
{
  extern __shared__ __half smh[];
  __half* sA = smh;
  __half* sB = smh + D_STAGES*D_SA;
  constexpr int BK=64, KT=NN/BK;

  const int tid=threadIdx.x, lane=tid&31, warp=tid>>5;
  const int wm=warp>>1, wn=warp&1;
  const int bm=blockIdx.y*128, bn=blockIdx.x*128;
  const float alpha = (bm<NN)? a0 : a1;
  const bool dosub = (subh!=nullptr) && (bm<NN);

  float acc[2][8][4];
  #pragma unroll
  for(int i=0;i<2;i++)
    #pragma unroll
    for(int j=0;j<8;j++)
      #pragma unroll
      for(int q=0;q<4;q++) acc[i][j][q]=0.f;

  auto loadA=[&](int st,int k0){
    __half* base=sA+st*D_SA;
    #pragma unroll
    for(int i=0;i<4;i++){
      int c=tid+i*256, r=c>>3, ch=c&7;
      cpa16(saddr(base+r*D_LDA+ch*8), A+(size_t)(bm+r)*NN+k0+ch*8);
    }
  };
  auto loadB=[&](int st,int k0){
    __half* base=sB+st*D_SB;
    #pragma unroll
    for(int i=0;i<4;i++){
      int c=tid+i*256, r=c>>4, ch=c&15;
      cpa16(saddr(base+r*D_LDB+ch*8), Bm+(size_t)(k0+r)*CC+bn+ch*8);
    }
  };

  loadA(0,0);    loadB(0,0);    cpcommit();
  loadA(1,BK);   loadB(1,BK);   cpcommit();

  int st=0;
  for(int kt=0;kt<KT;kt++){
    cpwait<1>();
    __syncthreads();
    const int lb=kt+2;
    if(lb<KT){
      int ls=lb%3;
      loadA(ls, lb*BK); loadB(ls, lb*BK);
    }
    cpcommit();
    const __half* a0p=sA+st*D_SA;
    const __half* b0p=sB+st*D_SB;
    st++; if(st==3) st=0;
    #pragma unroll
    for(int ks=0;ks<4;ks++){
      uint32_t af[2][4];
      #pragma unroll
      for(int mi=0;mi<2;mi++){
        int row=wm*32+mi*16+(lane&7)+((lane>>3)&1)*8;
        int col=ks*16+((lane>>4)&1)*8;
        ldsm4(af[mi], saddr(a0p+row*D_LDA+col));
      }
      uint32_t bf[8][2];
      #pragma unroll
      for(int nj=0;nj<4;nj++){
        int kr=ks*16+((lane>>3)&1)*8+(lane&7);
        int nc=wn*64+nj*16+((lane>>4)&1)*8;
        uint32_t t[4];
        ldsm4t(t, saddr(b0p+kr*D_LDB+nc));
        bf[2*nj][0]=t[0]; bf[2*nj][1]=t[1];
        bf[2*nj+1][0]=t[2]; bf[2*nj+1][1]=t[3];
      }
      #pragma unroll
      for(int mi=0;mi<2;mi++)
        #pragma unroll
        for(int nj=0;nj<8;nj++)
          mma16816(acc[mi][nj], af[mi], bf[nj]);
    }
  }

  #pragma unroll
  for(int mi=0;mi<2;mi++)
    #pragma unroll
    for(int nj=0;nj<8;nj++){
      int r0=bm+wm*32+mi*16+(lane>>2);
      int c0=bn+wn*64+nj*8+2*(lane&3);
      #pragma unroll
      for(int h=0;h<2;h++){
        int rr=r0+h*8;
        float v0=acc[mi][nj][2*h]*alpha;
        float v1=acc[mi][nj][2*h+1]*alpha;
        size_t idx=(size_t)rr*CC+c0;
        if(dosub){
          __half2 s=*(const __half2*)(subh+idx);
          v0-=__low2float(s); v1-=__high2float(s);
        }
        *(__half2*)(Ch+idx)=__floats2half2_rn(v0,v1);
      }
    }
}

// ---------------- output GEMM ----------------
// EP1: s=sigmoid(acc+bias); cc<64: x0w[state col]=half(s*hx); cc>=64: g_Value=s
// EP2: c=tanh(acc+bias); u=g_Value; out = u*hx+(1-u)*c
template<int BN, int EP>
__global__ void __launch_bounds__(256) k_ogemm(
    const __half* __restrict__ x0r, __half* __restrict__ x0w,
    const __half* __restrict__ W2,
    const float* __restrict__ bias,
    const float* __restrict__ hx, float* __restrict__ outp)
{
  constexpr int BK=16, KT=25;
  constexpr int LDA_S=24, LDB_S=BN+8;
  constexpr int WN=BN/2, NF=WN/8;

  __shared__ __half sA[2][128*LDA_S];
  __shared__ __half sB[2][BK*LDB_S];

  const int tid=threadIdx.x, lane=tid&31, warp=tid>>5;
  const int wm=warp>>1, wn=warp&1;
  const int b=blockIdx.y>>5;
  const int n0=(blockIdx.y&31)<<7;
  const int boff=b*66;

  float acc[2][NF][4];
  #pragma unroll
  for(int i=0;i<2;i++)
    #pragma unroll
    for(int j=0;j<NF;j++)
      #pragma unroll
      for(int q=0;q<4;q++) acc[i][j][q]=0.f;

  auto loadA=[&](int st,int kt){
    const int m=kt/5, f0=(kt%5)*16;
    const __half* Xm = (m==0)? x0r : g_Xh[m];
    #pragma unroll
    for(int i=0;i<4;i++){
      int c=tid+i*256, r=c>>3, w=c&7;
      int f=f0+w*2;
      int ok=(f<66);
      int fs=ok?f:0;
      cpa4z(saddr(&sA[st][r*LDA_S+w*2]),
            Xm+(size_t)(n0+r)*CC+boff+fs, ok?4:0);
    }
  };
  auto loadB=[&](int st,int k0){
    constexpr int CH=BN/8;
    if(tid<BK*CH){
      int r=tid/CH, ch=tid%CH;
      cpa16(saddr(&sB[st][r*LDB_S+ch*8]), W2+(size_t)(k0+r)*BN+ch*8);
    }
  };

  loadA(0,0); loadB(0,0); cpcommit();

  for(int kt=0;kt<KT;kt++){
    if(kt+1<KT){
      loadA((kt+1)&1,kt+1); loadB((kt+1)&1,(kt+1)*BK);
      cpcommit(); cpwait<1>();
    } else cpwait<0>();
    __syncthreads();
    const int st=kt&1;
    uint32_t af[2][4];
    #pragma unroll
    for(int mi=0;mi<2;mi++){
      int row=wm*32+mi*16+(lane&7)+((lane>>3)&1)*8;
      int col=((lane>>4)&1)*8;
      ldsm4(af[mi], saddr(&sA[st][row*LDA_S+col]));
    }
    uint32_t bf[NF][2];
    #pragma unroll
    for(int nj=0;nj<NF/2;nj++){
      int kr=((lane>>3)&1)*8+(lane&7);
      int nc=wn*WN+nj*16+((lane>>4)&1)*8;
      uint32_t t[4];
      ldsm4t(t, saddr(&sB[st][kr*LDB_S+nc]));
      bf[2*nj][0]=t[0]; bf[2*nj][1]=t[1];
      bf[2*nj+1][0]=t[2]; bf[2*nj+1][1]=t[3];
    }
    #pragma unroll
    for(int mi=0;mi<2;mi++)
      #pragma unroll
      for(int nj=0;nj<NF;nj++)
        mma16816(acc[mi][nj], af[mi], bf[nj]);
    __syncthreads();
  }

  #pragma unroll
  for(int mi=0;mi<2;mi++)
    #pragma unroll
    for(int nj=0;nj<NF;nj++){
      int rl0=wm*32+mi*16+(lane>>2);
      int c0=wn*WN+nj*8+2*(lane&3);
      #pragma unroll
      for(int q=0;q<4;q++){
        int n=n0+rl0+(q>>1)*8, cc=c0+(q&1);
        float v=acc[mi][nj][q];
        size_t vr=(size_t)b*NN+n;
        if(EP==1){
          float s=1.f/(1.f+expf(-(v+bias[cc])));
          if(cc<64){
            float h=hx[vr*UNITS+cc];
            x0w[(size_t)n*CC + boff + 2 + cc] = __float2half(s*h);
          } else {
            g_Value[vr*64+(cc-64)]=s;
          }
        } else {
          float cg=tanhf(v+bias[cc]);
          float u=g_Value[vr*64+cc];
          size_t oidx=vr*UNITS+cc;
          float h=hx[oidx];
          outp[oidx]=u*h+(1.f-u)*cg;
        }
      }
    }
}

// ---------------- glue: merged conversions (S + both W) ----------------
__global__ void k_conv(const float4* __restrict__ S4,
                       const float* __restrict__ wfn, const float* __restrict__ wg){
  size_t stride=(size_t)gridDim.x*blockDim.x;
  size_t tid0=(size_t)blockIdx.x*blockDim.x+threadIdx.x;
  size_t tot=(size_t)2*NN*NN/4;
  for(size_t i=tid0; i<tot; i+=stride){
    float4 v=S4[i];
    __half2 a=__floats2half2_rn(v.x*SSCALE,v.y*SSCALE);
    __half2 b=__floats2half2_rn(v.z*SSCALE,v.w*SSCALE);
    uint2 o; o.x=*(uint32_t*)&a; o.y=*(uint32_t*)&b;
    *(uint2*)&g_S16[i*4]=o;
  }
  // weights (small): first 51200 threads handle W2fn, first 25600 handle W2g
  if(tid0<KOUT_K*128){
    int k=(int)tid0>>7, o=(int)tid0&127;
    int m=k/80, f=k%80;
    g_W2fn[tid0]=(f<66)?__float2half(wfn[(f*5+m)*128+o]):__float2half(0.f);
  }
  if(tid0<KOUT_K*64){
    int k=(int)tid0>>6, o=(int)tid0&63;
    int m=k/80, f=k%80;
    g_W2g[tid0]=(f<66)?__float2half(wg[(f*5+m)*64+o]):__float2half(0.f);
  }
}

// round-0 pack: x0a full (inputs+hx); x0b inputs cols only (state cols written by EP1)
__global__ void k_pack(const float* __restrict__ inputs, const float* __restrict__ hx,
                       __half* __restrict__ x0a, __half* __restrict__ x0b)
{
  int n=blockIdx.x, tid=threadIdx.x;
  __shared__ float s[64][65];
  for(int i=tid;i<64*64;i+=256){
    int b=i>>6, j=i&63;
    s[j][b]=hx[(size_t)b*((size_t)NN*UNITS)+(size_t)n*64+j];
  }
  __syncthreads();
  size_t base=(size_t)n*CC;
  for(int i=tid;i<CC;i+=256){
    int b=i/66, f=i-66*b;
    float v=(f<2)?inputs[(size_t)b*(NN*2)+n*2+f]:s[f-2][b];
    __half hv=__float2half(v);
    x0a[base+i]=hv;
    if(f<2) x0b[base+i]=hv;
  }
}

// ---------------- launcher ----------------
extern "C" void kernel_launch(void* const* d_in, const int* in_sizes, int n_in,
                              void* d_out, int out_size) {
  const float* inputs=(const float*)d_in[0];
  const float* hx    =(const float*)d_in[1];
  const float* sup   =(const float*)d_in[2];
  const float* wfn   =(const float*)d_in[3];
  const float* bfn   =(const float*)d_in[4];
  const float* wg    =(const float*)d_in[5];
  const float* bg    =(const float*)d_in[6];
  float* outp=(float*)d_out;

  cudaFuncSetAttribute(k_dgemm, cudaFuncAttributeMaxDynamicSharedMemorySize, D_SMEM);

  void *pS,*pXh,*pWfn,*pWg;
  cudaGetSymbolAddress(&pS,g_S16);
  cudaGetSymbolAddress(&pXh,g_Xh);
  cudaGetSymbolAddress(&pWfn,g_W2fn);
  cudaGetSymbolAddress(&pWg,g_W2g);
  __half* S16=(__half*)pS;
  __half* Xh =(__half*)pXh;
  __half* Wfn=(__half*)pWfn;
  __half* Wg =(__half*)pWg;

  __half* P0=Xh;                 // x0 round 0
  __half* P1=Xh+1*XSTR;
  __half* P3=Xh+3*XSTR;
  __half* P5=Xh+5*XSTR;          // x0 round 1 (inputs prefilled; state from EP1)

  const size_t SZ=(size_t)NN*NN;

  // side stream for the conversions, overlapped with pack0; join before dgemm #1
  static cudaStream_t s2=nullptr;
  static cudaEvent_t eFork=nullptr, eConv=nullptr;
  if(!s2){
    cudaStreamCreateWithFlags(&s2, cudaStreamNonBlocking);
    cudaEventCreateWithFlags(&eFork, cudaEventDisableTiming);
    cudaEventCreateWithFlags(&eConv, cudaEventDisableTiming);
  }

  dim3 g1(CC/128, NN/128);       // (33, 32)  single support
  dim3 g23(CC/128, 2*NN/128);    // (33, 64)  fused S0|S1
  dim3 gOut(1, 2048);

  cudaEventRecord(eFork, 0);
  cudaStreamWaitEvent(s2, eFork, 0);
  k_conv<<<2048,256,0,s2>>>((const float4*)sup, wfn, wg);
  cudaEventRecord(eConv, s2);

  k_pack<<<NN,256>>>(inputs,hx, P0, P5);
  cudaStreamWaitEvent(0, eConv, 0);

  // round 0 (x0 = P0)
  k_dgemm<<<g1,256,D_SMEM>>>(S16, P0, 1.f/SSCALE, 0.f, nullptr, P1);
  k_dgemm<<<g23,256,D_SMEM>>>(S16, P1, 2.f/SSCALE, 1.f/SSCALE, P0, Xh+2*XSTR);
  k_dgemm<<<g1,256,D_SMEM>>>(S16+SZ, P3, 2.f/SSCALE, 0.f, P1, Xh+4*XSTR);
  // EP1: gates; writes r*hx -> P5 state cols, u -> g_Value
  k_ogemm<128,1><<<gOut,256>>>(P0, P5, Wfn, bfn, hx, nullptr);

  // round 1 (x0 = P5)
  k_dgemm<<<g1,256,D_SMEM>>>(S16, P5, 1.f/SSCALE, 0.f, nullptr, P1);
  k_dgemm<<<g23,256,D_SMEM>>>(S16, P1, 2.f/SSCALE, 1.f/SSCALE, P5, Xh+2*XSTR);
  k_dgemm<<<g1,256,D_SMEM>>>(S16+SZ, P3, 2.f/SSCALE, 0.f, P1, Xh+4*XSTR);
  // EP2: final GRU combine
  k_ogemm<64,2><<<gOut,256>>>(P5, nullptr, Wg, bg, hx, outp);
}